// round 16
// baseline (speedup 1.0000x reference)
#include <cuda_runtime.h>
#include <cstdint>

// GraphHeteroAtt via mma.sync m16n8k8 tf32 (compute_103-safe).
// U[n] = lrelu( (sum_k w_k[n] * H[k,n,:] @ Wuh[k]) / (sum_k w_k[n]) )
// w_k[n] = exp(lrelu( (H[k,n,:]@Wgh[k]) . (vt[n,:]@Wgv) ) / 8)
//
// R15 (measured best, 316us): 3 CTAs/SM, gk parked in smem, single H buffer,
// 528B pitch. Delta: L2 software prefetch of the NEXT H tile (1 line/thread)
// at the top of each k iteration -> the exposed cp.async refill hits L2.

#define KH 8
#define HD 128
#define GD 64
#define ROWP 528u

// ---------------- helpers ----------------
__device__ __forceinline__ uint32_t smem_u32(const void* p) {
    uint32_t a;
    asm("{ .reg .u64 t; cvta.to.shared.u64 t, %1; cvt.u32.u64 %0, t; }"
        : "=r"(a) : "l"(p));
    return a;
}
__device__ __forceinline__ float tf32r(float x) {
    uint32_t u;
    asm("cvt.rna.tf32.f32 %0, %1;" : "=r"(u) : "f"(x));
    return __uint_as_float(u);
}
__device__ __forceinline__ uint32_t tf32u(float x) {
    uint32_t u;
    asm("cvt.rna.tf32.f32 %0, %1;" : "=r"(u) : "f"(x));
    return u;
}
__device__ __forceinline__ void sts128(uint32_t a, float4 v) {
    asm volatile("st.shared.v4.f32 [%0], {%1, %2, %3, %4};"
                 :: "r"(a), "f"(v.x), "f"(v.y), "f"(v.z), "f"(v.w) : "memory");
}
__device__ __forceinline__ void sts32(uint32_t a, float v) {
    asm volatile("st.shared.f32 [%0], %1;" :: "r"(a), "f"(v) : "memory");
}
__device__ __forceinline__ float lds32(uint32_t a) {
    float v;
    asm volatile("ld.shared.f32 %0, [%1];" : "=f"(v) : "r"(a));
    return v;
}
__device__ __forceinline__ void ldsm4(uint32_t r[4], uint32_t a) {
    asm volatile("ldmatrix.sync.aligned.m8n8.x4.shared.b16 {%0,%1,%2,%3}, [%4];"
                 : "=r"(r[0]), "=r"(r[1]), "=r"(r[2]), "=r"(r[3]) : "r"(a));
}
__device__ __forceinline__ void mma8(float c[4], const uint32_t a[4], uint32_t b0, uint32_t b1) {
    asm volatile(
        "mma.sync.aligned.m16n8k8.row.col.f32.tf32.tf32.f32 "
        "{%0,%1,%2,%3}, {%4,%5,%6,%7}, {%8,%9}, {%0,%1,%2,%3};"
        : "+f"(c[0]), "+f"(c[1]), "+f"(c[2]), "+f"(c[3])
        : "r"(a[0]), "r"(a[1]), "r"(a[2]), "r"(a[3]), "r"(b0), "r"(b1));
}

// ---------------- fragment-ordered weights (float4 = 2 adjacent n-tiles) ----------------
__device__ float4 WgvF[2048];          // 16 kt * 4 npair * 32
__device__ float4 WghF[KH * 2048];
__device__ float4 WuhF[KH * 4096];     // 16 kt * 8 npair * 32

__global__ void prep_kernel(const float* __restrict__ Wgv,
                            const float* __restrict__ Wgh,
                            const float* __restrict__ Wuh) {
    int i = blockIdx.x * 256 + threadIdx.x;
    if (i < 2048) {
        int p = i;
        int kt = p >> 7, npair = (p >> 5) & 3, lane = p & 31;
        int gid = lane >> 2, tig = lane & 3;
        int r0 = kt * 8 + tig;
        int c0 = (npair * 2) * 8 + gid, c1 = (npair * 2 + 1) * 8 + gid;
        WgvF[p] = make_float4(tf32r(Wgv[r0 * GD + c0]), tf32r(Wgv[(r0 + 4) * GD + c0]),
                              tf32r(Wgv[r0 * GD + c1]), tf32r(Wgv[(r0 + 4) * GD + c1]));
    } else if (i < 2048 + KH * 2048) {
        int j = i - 2048;
        int k = j >> 11, p = j & 2047;
        int kt = p >> 7, npair = (p >> 5) & 3, lane = p & 31;
        int gid = lane >> 2, tig = lane & 3;
        int r0 = kt * 8 + tig;
        int c0 = (npair * 2) * 8 + gid, c1 = (npair * 2 + 1) * 8 + gid;
        const float* b = Wgh + k * HD * GD;
        WghF[k * 2048 + p] = make_float4(tf32r(b[r0 * GD + c0]), tf32r(b[(r0 + 4) * GD + c0]),
                                         tf32r(b[r0 * GD + c1]), tf32r(b[(r0 + 4) * GD + c1]));
    } else if (i < 2048 + KH * 2048 + KH * 4096) {
        int j = i - 2048 - KH * 2048;
        int k = j >> 12, p = j & 4095;
        int kt = p >> 8, npair = (p >> 5) & 7, lane = p & 31;
        int gid = lane >> 2, tig = lane & 3;
        int r0 = kt * 8 + tig;
        int c0 = (npair * 2) * 8 + gid, c1 = (npair * 2 + 1) * 8 + gid;
        const float* b = Wuh + k * HD * HD;
        WuhF[k * 4096 + p] = make_float4(tf32r(b[r0 * HD + c0]), tf32r(b[(r0 + 4) * HD + c0]),
                                         tf32r(b[r0 * HD + c1]), tf32r(b[(r0 + 4) * HD + c1]));
    }
}

// ---------------- smem layout (per CTA, 3 CTAs/SM) ----------------
// A  @ 0     : 64 rows x 528 B = 33792
// GK @ 33792 : 16 x 256 f32 gk-fragment park = 16384
// DS @ 50176 : 4 n-quarter partials x 64 rows x 4B = 1024
#define SMEM_GK    33792u
#define SMEM_DS    50176u
#define SMEM_TOTAL 51200u

__global__ void __launch_bounds__(256, 3)
het_main(const float* __restrict__ vt, const float* __restrict__ Hin,
         float* __restrict__ out, int Nn) {
    extern __shared__ char smem_raw[];
    const uint32_t A  = smem_u32(smem_raw);
    const uint32_t GK = A + SMEM_GK;
    const uint32_t DS = A + SMEM_DS;

    const int tid  = threadIdx.x;
    const int warp = tid >> 5;
    const int lane = tid & 31;
    const int gid  = lane >> 2;
    const int tig  = lane & 3;
    const int rg   = warp >> 2;      // row group (32 rows each)
    const int q    = warp & 3;       // n-quarter
    const int base = blockIdx.x << 6;

    // ldmatrix lane addressing (pitch layout; per-kt offset = kt*32 immediate)
    const int tsel = lane >> 3;
    const int trow = lane & 7;
    const int csel = tsel >> 1;
    const int rsub = ((tsel & 1) << 3) + trow;
    const uint32_t rowoff0 = (uint32_t)(rg * 32 + rsub) * ROWP + (uint32_t)(csel << 4) + A;
    const uint32_t rowoff1 = rowoff0 + 16u * ROWP;

    // this thread's node (for L2-prefetch bounds) — line tid covers node base+tid/4
    const bool pf_ok = (base + (tid >> 2)) < Nn;

    // async fill of the single 64x128 raw H tile
    auto prefetch = [&](const float* src) {
#pragma unroll
        for (int j = 0; j < 8; j++) {
            int idx = j * 256 + tid;
            int row = idx >> 5, ch = idx & 31;
            int node = base + row;
            const float* s = src + (size_t)(node < Nn ? node : 0) * HD + ch * 4;
            uint32_t d = A + (uint32_t)row * ROWP + (uint32_t)(ch << 4);
            int sz = (node < Nn) ? 16 : 0;
            asm volatile("cp.async.cg.shared.global [%0], [%1], 16, %2;"
                         :: "r"(d), "l"(s), "r"(sz) : "memory");
        }
        asm volatile("cp.async.commit_group;" ::: "memory");
    };

    // ---------------- prologue ----------------
    {   // stage vt tile synchronously into A (raw; CVT at frag load)
        const float4* vp = (const float4*)vt;
#pragma unroll
        for (int j = 0; j < 8; j++) {
            int idx = j * 256 + tid;
            int row = idx >> 5, ch = idx & 31;
            int node = base + row;
            float4 v = make_float4(0.f, 0.f, 0.f, 0.f);
            if (node < Nn) v = vp[(size_t)node * 32 + ch];
            sts128(A + (uint32_t)row * ROWP + (uint32_t)(ch << 4), v);
        }
    }
    __syncthreads();

    // gk fragments -> park in GK smem (transient registers)
    {
        float gkf[16];
#pragma unroll
        for (int i = 0; i < 16; i++) gkf[i] = 0.f;
        const float4* bg = &WgvF[q * 32 + lane];
#pragma unroll
        for (int kt = 0; kt < 16; kt++) {
            uint32_t r0[4], r1[4], a0[4], a1[4];
            ldsm4(r0, rowoff0 + (uint32_t)(kt * 32));
            ldsm4(r1, rowoff1 + (uint32_t)(kt * 32));
#pragma unroll
            for (int i = 0; i < 4; i++) {
                a0[i] = tf32u(__uint_as_float(r0[i]));
                a1[i] = tf32u(__uint_as_float(r1[i]));
            }
            float4 b = __ldg(bg);  bg += 128;
            uint32_t b0 = __float_as_uint(b.x), b1 = __float_as_uint(b.y);
            uint32_t b2 = __float_as_uint(b.z), b3 = __float_as_uint(b.w);
            mma8(&gkf[0],  a0, b0, b1);  mma8(&gkf[4],  a0, b2, b3);
            mma8(&gkf[8],  a1, b0, b1);  mma8(&gkf[12], a1, b2, b3);
        }
#pragma unroll
        for (int i = 0; i < 16; i++)
            sts32(GK + (uint32_t)(i * 256 + tid) * 4u, gkf[i]);   // same-thread readback
    }
    __syncthreads();                        // all gk GEMMs done; A reusable

    prefetch(Hin);                          // H[0]
    asm volatile("cp.async.wait_group 0;" ::: "memory");
    __syncthreads();

    // ---------------- main loop ----------------
    float uacc[2][4][4];
#pragma unroll
    for (int mt = 0; mt < 2; mt++)
#pragma unroll
        for (int n = 0; n < 4; n++)
#pragma unroll
            for (int qq = 0; qq < 4; qq++) uacc[mt][n][qq] = 0.f;
    float Z[2][2] = {{0.f, 0.f}, {0.f, 0.f}};

    for (int k = 0; k < KH; k++) {
        // ---- L2 prefetch of next H tile (contiguous 32KB; 1 line/thread) ----
        if (k + 1 < KH && pf_ok) {
            const char* pf = (const char*)(Hin + (size_t)(k + 1) * (size_t)Nn * HD)
                           + (size_t)base * 512 + (size_t)tid * 128;
            asm volatile("prefetch.global.L2 [%0];" :: "l"(pf));
        }

        // ---- GEMM1: g_query partials (CVT per fragment, R5 recipe) ----
        float c1[2][2][4];
#pragma unroll
        for (int mt = 0; mt < 2; mt++)
#pragma unroll
            for (int n = 0; n < 2; n++)
#pragma unroll
                for (int qq = 0; qq < 4; qq++) c1[mt][n][qq] = 0.f;
        {
            const float4* bg = &WghF[k * 2048 + q * 32 + lane];
#pragma unroll
            for (int kt = 0; kt < 16; kt++) {
                uint32_t r0[4], r1[4], a0[4], a1[4];
                ldsm4(r0, rowoff0 + (uint32_t)(kt * 32));
                ldsm4(r1, rowoff1 + (uint32_t)(kt * 32));
#pragma unroll
                for (int i = 0; i < 4; i++) {
                    a0[i] = tf32u(__uint_as_float(r0[i]));
                    a1[i] = tf32u(__uint_as_float(r1[i]));
                }
                float4 b = __ldg(bg);  bg += 128;
                uint32_t b0 = __float_as_uint(b.x), b1 = __float_as_uint(b.y);
                uint32_t b2 = __float_as_uint(b.z), b3 = __float_as_uint(b.w);
                mma8(c1[0][0], a0, b0, b1);  mma8(c1[0][1], a0, b2, b3);
                mma8(c1[1][0], a1, b0, b1);  mma8(c1[1][1], a1, b2, b3);
            }
        }

        // ---- dot with parked gk, lane-reduce, publish quarter partials ----
#pragma unroll
        for (int mt = 0; mt < 2; mt++) {
            float d0 = 0.f, d1 = 0.f;
#pragma unroll
            for (int n = 0; n < 2; n++) {
                int i = (mt * 2 + n) * 4;
                float g0 = lds32(GK + (uint32_t)((i + 0) * 256 + tid) * 4u);
                float g1 = lds32(GK + (uint32_t)((i + 1) * 256 + tid) * 4u);
                float g2 = lds32(GK + (uint32_t)((i + 2) * 256 + tid) * 4u);
                float g3 = lds32(GK + (uint32_t)((i + 3) * 256 + tid) * 4u);
                d0 = fmaf(c1[mt][n][0], g0, fmaf(c1[mt][n][1], g1, d0));
                d1 = fmaf(c1[mt][n][2], g2, fmaf(c1[mt][n][3], g3, d1));
            }
            d0 += __shfl_xor_sync(0xffffffffu, d0, 1);
            d0 += __shfl_xor_sync(0xffffffffu, d0, 2);
            d1 += __shfl_xor_sync(0xffffffffu, d1, 1);
            d1 += __shfl_xor_sync(0xffffffffu, d1, 2);
            if (tig == 0) {
                int row = rg * 32 + mt * 16 + gid;
                sts32(DS + (uint32_t)(q * 64 + row) * 4u, d0);
                sts32(DS + (uint32_t)(q * 64 + row + 8) * 4u, d1);
            }
        }
        __syncthreads();

        // ---- combine quarters -> w per row ----
        float wgt[2][2];
#pragma unroll
        for (int mt = 0; mt < 2; mt++) {
            int row = rg * 32 + mt * 16 + gid;
            float d0 = lds32(DS + (uint32_t)row * 4u)
                     + lds32(DS + (uint32_t)(64 + row) * 4u)
                     + lds32(DS + (uint32_t)(128 + row) * 4u)
                     + lds32(DS + (uint32_t)(192 + row) * 4u);
            float d1 = lds32(DS + (uint32_t)(row + 8) * 4u)
                     + lds32(DS + (uint32_t)(64 + row + 8) * 4u)
                     + lds32(DS + (uint32_t)(128 + row + 8) * 4u)
                     + lds32(DS + (uint32_t)(192 + row + 8) * 4u);
            float l0 = d0 >= 0.f ? d0 : 0.01f * d0;
            float l1 = d1 >= 0.f ? d1 : 0.01f * d1;
            wgt[mt][0] = __expf(l0 * 0.125f);
            wgt[mt][1] = __expf(l1 * 0.125f);
            Z[mt][0] += wgt[mt][0];
            Z[mt][1] += wgt[mt][1];
        }

        // ---- GEMM2: U += (w .* H) @ Wuh[k] (tf32(raw*w), R5 recipe) ----
        {
            const float4* bu = &WuhF[k * 4096 + q * 64 + lane];
#pragma unroll
            for (int kt = 0; kt < 16; kt++) {
                uint32_t r0[4], r1[4], a0[4], a1[4];
                ldsm4(r0, rowoff0 + (uint32_t)(kt * 32));
                ldsm4(r1, rowoff1 + (uint32_t)(kt * 32));
                a0[0] = tf32u(__uint_as_float(r0[0]) * wgt[0][0]);
                a0[1] = tf32u(__uint_as_float(r0[1]) * wgt[0][1]);
                a0[2] = tf32u(__uint_as_float(r0[2]) * wgt[0][0]);
                a0[3] = tf32u(__uint_as_float(r0[3]) * wgt[0][1]);
                a1[0] = tf32u(__uint_as_float(r1[0]) * wgt[1][0]);
                a1[1] = tf32u(__uint_as_float(r1[1]) * wgt[1][1]);
                a1[2] = tf32u(__uint_as_float(r1[2]) * wgt[1][0]);
                a1[3] = tf32u(__uint_as_float(r1[3]) * wgt[1][1]);
                float4 bA = __ldg(bu);
                float4 bB = __ldg(bu + 32);  bu += 256;
                uint32_t u0 = __float_as_uint(bA.x), u1 = __float_as_uint(bA.y);
                uint32_t u2 = __float_as_uint(bA.z), u3 = __float_as_uint(bA.w);
                uint32_t u4 = __float_as_uint(bB.x), u5 = __float_as_uint(bB.y);
                uint32_t u6 = __float_as_uint(bB.z), u7 = __float_as_uint(bB.w);
                mma8(uacc[0][0], a0, u0, u1);  mma8(uacc[0][1], a0, u2, u3);
                mma8(uacc[0][2], a0, u4, u5);  mma8(uacc[0][3], a0, u6, u7);
                mma8(uacc[1][0], a1, u0, u1);  mma8(uacc[1][1], a1, u2, u3);
                mma8(uacc[1][2], a1, u4, u5);  mma8(uacc[1][3], a1, u6, u7);
            }
        }

        // ---- refill the single buffer with H[k+1] (now L2-resident) ----
        if (k + 1 < KH) {
            __syncthreads();                 // all reads of A done
            prefetch(Hin + (size_t)(k + 1) * (size_t)Nn * HD);
            asm volatile("cp.async.wait_group 0;" ::: "memory");
            __syncthreads();                 // H[k+1] resident
        }
    }

    // ---------------- epilogue ----------------
#pragma unroll
    for (int mt = 0; mt < 2; mt++) {
        float inv0 = 1.0f / Z[mt][0];
        float inv1 = 1.0f / Z[mt][1];
        int node0 = base + rg * 32 + mt * 16 + gid;
        int node1 = node0 + 8;
        if (node0 < Nn) {
            float2* op = (float2*)(out + (size_t)node0 * HD + q * 32);
#pragma unroll
            for (int n = 0; n < 4; n++) {
                float v0 = uacc[mt][n][0] * inv0;
                float v1 = uacc[mt][n][1] * inv0;
                float2 o;
                o.x = v0 >= 0.f ? v0 : 0.01f * v0;
                o.y = v1 >= 0.f ? v1 : 0.01f * v1;
                op[n * 4 + tig] = o;
            }
        }
        if (node1 < Nn) {
            float2* op = (float2*)(out + (size_t)node1 * HD + q * 32);
#pragma unroll
            for (int n = 0; n < 4; n++) {
                float v0 = uacc[mt][n][2] * inv1;
                float v1 = uacc[mt][n][3] * inv1;
                float2 o;
                o.x = v0 >= 0.f ? v0 : 0.01f * v0;
                o.y = v1 >= 0.f ? v1 : 0.01f * v1;
                op[n * 4 + tig] = o;
            }
        }
    }
}

// ---------------- launch ----------------
extern "C" void kernel_launch(void* const* d_in, const int* in_sizes, int n_in,
                              void* d_out, int out_size) {
    const float* vt  = (const float*)d_in[0];
    const float* H   = (const float*)d_in[1];
    const float* Wgv = (const float*)d_in[2];
    const float* Wgh = (const float*)d_in[3];
    const float* Wuh = (const float*)d_in[4];
    float* out = (float*)d_out;

    int Nn = in_sizes[0] / HD;

    cudaFuncSetAttribute(het_main, cudaFuncAttributeMaxDynamicSharedMemorySize, SMEM_TOTAL);

    int total = 2048 + KH * 2048 + KH * 4096;   // 51200 prep threads
    prep_kernel<<<(total + 255) / 256, 256>>>(Wgv, Wgh, Wuh);

    int blocks = (Nn + 63) / 64;
    het_main<<<blocks, 256, SMEM_TOTAL>>>(vt, H, out, Nn);
}

// round 17
// speedup vs baseline: 1.1950x; 1.1950x over previous
#include <cuda_runtime.h>
#include <cstdint>

// GraphHeteroAtt via mma.sync m16n8k8 tf32 (compute_103-safe).
// U[n] = lrelu( (sum_k w_k[n] * H[k,n,:] @ Wuh[k]) / (sum_k w_k[n]) )
// w_k[n] = exp(lrelu( (H[k,n,:]@Wgh[k]) . (vt[n,:]@Wgv) ) / 8)
//
// R15 per-warp recipe at 32-node / 128-thread CTAs, 5 CTAs/SM (20 warps),
// WITH the double-buffered cp.async pipeline restored (no exposed refill).
// Warp = one col-quarter over the CTA's 32 rows; gk parked in smem.

#define KH 8
#define HD 128
#define GD 64
#define ROWP 528u

// ---------------- helpers ----------------
__device__ __forceinline__ uint32_t smem_u32(const void* p) {
    uint32_t a;
    asm("{ .reg .u64 t; cvta.to.shared.u64 t, %1; cvt.u32.u64 %0, t; }"
        : "=r"(a) : "l"(p));
    return a;
}
__device__ __forceinline__ float tf32r(float x) {
    uint32_t u;
    asm("cvt.rna.tf32.f32 %0, %1;" : "=r"(u) : "f"(x));
    return __uint_as_float(u);
}
__device__ __forceinline__ uint32_t tf32u(float x) {
    uint32_t u;
    asm("cvt.rna.tf32.f32 %0, %1;" : "=r"(u) : "f"(x));
    return u;
}
__device__ __forceinline__ void sts128(uint32_t a, float4 v) {
    asm volatile("st.shared.v4.f32 [%0], {%1, %2, %3, %4};"
                 :: "r"(a), "f"(v.x), "f"(v.y), "f"(v.z), "f"(v.w) : "memory");
}
__device__ __forceinline__ void sts32(uint32_t a, float v) {
    asm volatile("st.shared.f32 [%0], %1;" :: "r"(a), "f"(v) : "memory");
}
__device__ __forceinline__ float lds32(uint32_t a) {
    float v;
    asm volatile("ld.shared.f32 %0, [%1];" : "=f"(v) : "r"(a));
    return v;
}
__device__ __forceinline__ void ldsm4(uint32_t r[4], uint32_t a) {
    asm volatile("ldmatrix.sync.aligned.m8n8.x4.shared.b16 {%0,%1,%2,%3}, [%4];"
                 : "=r"(r[0]), "=r"(r[1]), "=r"(r[2]), "=r"(r[3]) : "r"(a));
}
__device__ __forceinline__ void mma8(float c[4], const uint32_t a[4], uint32_t b0, uint32_t b1) {
    asm volatile(
        "mma.sync.aligned.m16n8k8.row.col.f32.tf32.tf32.f32 "
        "{%0,%1,%2,%3}, {%4,%5,%6,%7}, {%8,%9}, {%0,%1,%2,%3};"
        : "+f"(c[0]), "+f"(c[1]), "+f"(c[2]), "+f"(c[3])
        : "r"(a[0]), "r"(a[1]), "r"(a[2]), "r"(a[3]), "r"(b0), "r"(b1));
}

// ---------------- fragment-ordered weights (float4 = 2 adjacent n-tiles) ----------------
__device__ float4 WgvF[2048];          // 16 kt * 4 npair * 32
__device__ float4 WghF[KH * 2048];
__device__ float4 WuhF[KH * 4096];     // 16 kt * 8 npair * 32

__global__ void prep_kernel(const float* __restrict__ Wgv,
                            const float* __restrict__ Wgh,
                            const float* __restrict__ Wuh) {
    int i = blockIdx.x * 256 + threadIdx.x;
    if (i < 2048) {
        int p = i;
        int kt = p >> 7, npair = (p >> 5) & 3, lane = p & 31;
        int gid = lane >> 2, tig = lane & 3;
        int r0 = kt * 8 + tig;
        int c0 = (npair * 2) * 8 + gid, c1 = (npair * 2 + 1) * 8 + gid;
        WgvF[p] = make_float4(tf32r(Wgv[r0 * GD + c0]), tf32r(Wgv[(r0 + 4) * GD + c0]),
                              tf32r(Wgv[r0 * GD + c1]), tf32r(Wgv[(r0 + 4) * GD + c1]));
    } else if (i < 2048 + KH * 2048) {
        int j = i - 2048;
        int k = j >> 11, p = j & 2047;
        int kt = p >> 7, npair = (p >> 5) & 3, lane = p & 31;
        int gid = lane >> 2, tig = lane & 3;
        int r0 = kt * 8 + tig;
        int c0 = (npair * 2) * 8 + gid, c1 = (npair * 2 + 1) * 8 + gid;
        const float* b = Wgh + k * HD * GD;
        WghF[k * 2048 + p] = make_float4(tf32r(b[r0 * GD + c0]), tf32r(b[(r0 + 4) * GD + c0]),
                                         tf32r(b[r0 * GD + c1]), tf32r(b[(r0 + 4) * GD + c1]));
    } else if (i < 2048 + KH * 2048 + KH * 4096) {
        int j = i - 2048 - KH * 2048;
        int k = j >> 12, p = j & 4095;
        int kt = p >> 8, npair = (p >> 5) & 7, lane = p & 31;
        int gid = lane >> 2, tig = lane & 3;
        int r0 = kt * 8 + tig;
        int c0 = (npair * 2) * 8 + gid, c1 = (npair * 2 + 1) * 8 + gid;
        const float* b = Wuh + k * HD * HD;
        WuhF[k * 4096 + p] = make_float4(tf32r(b[r0 * HD + c0]), tf32r(b[(r0 + 4) * HD + c0]),
                                         tf32r(b[r0 * HD + c1]), tf32r(b[(r0 + 4) * HD + c1]));
    }
}

// ---------------- smem layout (per CTA, 5 CTAs/SM) ----------------
// A0 @ 0     : 32 rows x 528 B = 16896
// A1 @ 16896 : 16896
// GK @ 33792 : 16 x 128 f32 gk-fragment park = 8192
// DS @ 41984 : 4 n-quarter partials x 32 rows x 4B = 512
#define ABUF_BYTES 16896u
#define SMEM_GK    33792u
#define SMEM_DS    41984u
#define SMEM_TOTAL 42496u

__global__ void __launch_bounds__(128, 5)
het_main(const float* __restrict__ vt, const float* __restrict__ Hin,
         float* __restrict__ out, int Nn) {
    extern __shared__ char smem_raw[];
    const uint32_t A0 = smem_u32(smem_raw);
    const uint32_t A1 = A0 + ABUF_BYTES;
    const uint32_t GK = A0 + SMEM_GK;
    const uint32_t DS = A0 + SMEM_DS;

    const int tid  = threadIdx.x;
    const int q    = tid >> 5;       // warp = col-quarter
    const int lane = tid & 31;
    const int gid  = lane >> 2;
    const int tig  = lane & 3;
    const int base = blockIdx.x << 5;   // 32 nodes per CTA

    // ldmatrix lane addressing (pitch layout; per-kt offset = kt*32 immediate)
    const int tsel = lane >> 3;
    const int trow = lane & 7;
    const int csel = tsel >> 1;
    const int rsub = ((tsel & 1) << 3) + trow;
    const uint32_t rowoff0 = (uint32_t)rsub * ROWP + (uint32_t)(csel << 4);
    const uint32_t rowoff1 = rowoff0 + 16u * ROWP;

    // async fill of one 32x128 raw H tile into buffer Ab
    auto prefetch = [&](uint32_t Ab, const float* src) {
#pragma unroll
        for (int j = 0; j < 8; j++) {
            int idx = j * 128 + tid;
            int row = idx >> 5, ch = idx & 31;
            int node = base + row;
            const float* s = src + (size_t)(node < Nn ? node : 0) * HD + ch * 4;
            uint32_t d = Ab + (uint32_t)row * ROWP + (uint32_t)(ch << 4);
            int sz = (node < Nn) ? 16 : 0;
            asm volatile("cp.async.cg.shared.global [%0], [%1], 16, %2;"
                         :: "r"(d), "l"(s), "r"(sz) : "memory");
        }
        asm volatile("cp.async.commit_group;" ::: "memory");
    };

    // ---------------- prologue ----------------
    prefetch(A1, Hin);                      // H[0] -> A1 (async)

    {   // stage vt tile synchronously into A0 (raw; CVT at frag load)
        const float4* vp = (const float4*)vt;
#pragma unroll
        for (int j = 0; j < 8; j++) {
            int idx = j * 128 + tid;
            int row = idx >> 5, ch = idx & 31;
            int node = base + row;
            float4 v = make_float4(0.f, 0.f, 0.f, 0.f);
            if (node < Nn) v = vp[(size_t)node * 32 + ch];
            sts128(A0 + (uint32_t)row * ROWP + (uint32_t)(ch << 4), v);
        }
    }
    __syncthreads();

    // gk fragments -> park in GK smem (transient registers)
    {
        float gkf[16];
#pragma unroll
        for (int i = 0; i < 16; i++) gkf[i] = 0.f;
        const float4* bg = &WgvF[q * 32 + lane];
#pragma unroll
        for (int kt = 0; kt < 16; kt++) {
            uint32_t r0[4], r1[4], a0[4], a1[4];
            ldsm4(r0, A0 + rowoff0 + (uint32_t)(kt * 32));
            ldsm4(r1, A0 + rowoff1 + (uint32_t)(kt * 32));
#pragma unroll
            for (int i = 0; i < 4; i++) {
                a0[i] = tf32u(__uint_as_float(r0[i]));
                a1[i] = tf32u(__uint_as_float(r1[i]));
            }
            float4 b = __ldg(bg);  bg += 128;
            uint32_t b0 = __float_as_uint(b.x), b1 = __float_as_uint(b.y);
            uint32_t b2 = __float_as_uint(b.z), b3 = __float_as_uint(b.w);
            mma8(&gkf[0],  a0, b0, b1);  mma8(&gkf[4],  a0, b2, b3);
            mma8(&gkf[8],  a1, b0, b1);  mma8(&gkf[12], a1, b2, b3);
        }
#pragma unroll
        for (int i = 0; i < 16; i++)
            sts32(GK + (uint32_t)(i * 128 + tid) * 4u, gkf[i]);   // same-thread readback
    }
    asm volatile("cp.async.wait_group 0;" ::: "memory");
    __syncthreads();                        // H[0] resident in A1; A0 free

    // ---------------- main loop ----------------
    float uacc[2][4][4];
#pragma unroll
    for (int mt = 0; mt < 2; mt++)
#pragma unroll
        for (int n = 0; n < 4; n++)
#pragma unroll
            for (int qq = 0; qq < 4; qq++) uacc[mt][n][qq] = 0.f;
    float Z[2][2] = {{0.f, 0.f}, {0.f, 0.f}};

    for (int k = 0; k < KH; k++) {
        const uint32_t cur = (k & 1) ? A0 : A1;
        const uint32_t nxt = (k & 1) ? A1 : A0;
        if (k + 1 < KH) prefetch(nxt, Hin + (size_t)(k + 1) * (size_t)Nn * HD);

        // ---- GEMM1: g_query partials (CVT per fragment, R5 recipe) ----
        float c1[2][2][4];
#pragma unroll
        for (int mt = 0; mt < 2; mt++)
#pragma unroll
            for (int n = 0; n < 2; n++)
#pragma unroll
                for (int qq = 0; qq < 4; qq++) c1[mt][n][qq] = 0.f;
        {
            const float4* bg = &WghF[k * 2048 + q * 32 + lane];
#pragma unroll
            for (int kt = 0; kt < 16; kt++) {
                uint32_t r0[4], r1[4], a0[4], a1[4];
                ldsm4(r0, cur + rowoff0 + (uint32_t)(kt * 32));
                ldsm4(r1, cur + rowoff1 + (uint32_t)(kt * 32));
#pragma unroll
                for (int i = 0; i < 4; i++) {
                    a0[i] = tf32u(__uint_as_float(r0[i]));
                    a1[i] = tf32u(__uint_as_float(r1[i]));
                }
                float4 b = __ldg(bg);  bg += 128;
                uint32_t b0 = __float_as_uint(b.x), b1 = __float_as_uint(b.y);
                uint32_t b2 = __float_as_uint(b.z), b3 = __float_as_uint(b.w);
                mma8(c1[0][0], a0, b0, b1);  mma8(c1[0][1], a0, b2, b3);
                mma8(c1[1][0], a1, b0, b1);  mma8(c1[1][1], a1, b2, b3);
            }
        }

        // ---- dot with parked gk, lane-reduce, publish quarter partials ----
#pragma unroll
        for (int mt = 0; mt < 2; mt++) {
            float d0 = 0.f, d1 = 0.f;
#pragma unroll
            for (int n = 0; n < 2; n++) {
                int i = (mt * 2 + n) * 4;
                float g0 = lds32(GK + (uint32_t)((i + 0) * 128 + tid) * 4u);
                float g1 = lds32(GK + (uint32_t)((i + 1) * 128 + tid) * 4u);
                float g2 = lds32(GK + (uint32_t)((i + 2) * 128 + tid) * 4u);
                float g3 = lds32(GK + (uint32_t)((i + 3) * 128 + tid) * 4u);
                d0 = fmaf(c1[mt][n][0], g0, fmaf(c1[mt][n][1], g1, d0));
                d1 = fmaf(c1[mt][n][2], g2, fmaf(c1[mt][n][3], g3, d1));
            }
            d0 += __shfl_xor_sync(0xffffffffu, d0, 1);
            d0 += __shfl_xor_sync(0xffffffffu, d0, 2);
            d1 += __shfl_xor_sync(0xffffffffu, d1, 1);
            d1 += __shfl_xor_sync(0xffffffffu, d1, 2);
            if (tig == 0) {
                int row = mt * 16 + gid;
                sts32(DS + (uint32_t)(q * 32 + row) * 4u, d0);
                sts32(DS + (uint32_t)(q * 32 + row + 8) * 4u, d1);
            }
        }
        __syncthreads();

        // ---- combine quarters -> w per row ----
        float wgt[2][2];
#pragma unroll
        for (int mt = 0; mt < 2; mt++) {
            int row = mt * 16 + gid;
            float d0 = lds32(DS + (uint32_t)row * 4u)
                     + lds32(DS + (uint32_t)(32 + row) * 4u)
                     + lds32(DS + (uint32_t)(64 + row) * 4u)
                     + lds32(DS + (uint32_t)(96 + row) * 4u);
            float d1 = lds32(DS + (uint32_t)(row + 8) * 4u)
                     + lds32(DS + (uint32_t)(32 + row + 8) * 4u)
                     + lds32(DS + (uint32_t)(64 + row + 8) * 4u)
                     + lds32(DS + (uint32_t)(96 + row + 8) * 4u);
            float l0 = d0 >= 0.f ? d0 : 0.01f * d0;
            float l1 = d1 >= 0.f ? d1 : 0.01f * d1;
            wgt[mt][0] = __expf(l0 * 0.125f);
            wgt[mt][1] = __expf(l1 * 0.125f);
            Z[mt][0] += wgt[mt][0];
            Z[mt][1] += wgt[mt][1];
        }

        // ---- GEMM2: U += (w .* H) @ Wuh[k] (tf32(raw*w), R5 recipe) ----
        {
            const float4* bu = &WuhF[k * 4096 + q * 64 + lane];
#pragma unroll
            for (int kt = 0; kt < 16; kt++) {
                uint32_t r0[4], r1[4], a0[4], a1[4];
                ldsm4(r0, cur + rowoff0 + (uint32_t)(kt * 32));
                ldsm4(r1, cur + rowoff1 + (uint32_t)(kt * 32));
                a0[0] = tf32u(__uint_as_float(r0[0]) * wgt[0][0]);
                a0[1] = tf32u(__uint_as_float(r0[1]) * wgt[0][1]);
                a0[2] = tf32u(__uint_as_float(r0[2]) * wgt[0][0]);
                a0[3] = tf32u(__uint_as_float(r0[3]) * wgt[0][1]);
                a1[0] = tf32u(__uint_as_float(r1[0]) * wgt[1][0]);
                a1[1] = tf32u(__uint_as_float(r1[1]) * wgt[1][1]);
                a1[2] = tf32u(__uint_as_float(r1[2]) * wgt[1][0]);
                a1[3] = tf32u(__uint_as_float(r1[3]) * wgt[1][1]);
                float4 bA = __ldg(bu);
                float4 bB = __ldg(bu + 32);  bu += 256;
                uint32_t u0 = __float_as_uint(bA.x), u1 = __float_as_uint(bA.y);
                uint32_t u2 = __float_as_uint(bA.z), u3 = __float_as_uint(bA.w);
                uint32_t u4 = __float_as_uint(bB.x), u5 = __float_as_uint(bB.y);
                uint32_t u6 = __float_as_uint(bB.z), u7 = __float_as_uint(bB.w);
                mma8(uacc[0][0], a0, u0, u1);  mma8(uacc[0][1], a0, u2, u3);
                mma8(uacc[0][2], a0, u4, u5);  mma8(uacc[0][3], a0, u6, u7);
                mma8(uacc[1][0], a1, u0, u1);  mma8(uacc[1][1], a1, u2, u3);
                mma8(uacc[1][2], a1, u4, u5);  mma8(uacc[1][3], a1, u6, u7);
            }
        }

        if (k + 1 < KH) {
            asm volatile("cp.async.wait_group 0;" ::: "memory");
            __syncthreads();                 // nxt arrived; cur reads done
        }
    }

    // ---------------- epilogue ----------------
#pragma unroll
    for (int mt = 0; mt < 2; mt++) {
        float inv0 = 1.0f / Z[mt][0];
        float inv1 = 1.0f / Z[mt][1];
        int node0 = base + mt * 16 + gid;
        int node1 = node0 + 8;
        if (node0 < Nn) {
            float2* op = (float2*)(out + (size_t)node0 * HD + q * 32);
#pragma unroll
            for (int n = 0; n < 4; n++) {
                float v0 = uacc[mt][n][0] * inv0;
                float v1 = uacc[mt][n][1] * inv0;
                float2 o;
                o.x = v0 >= 0.f ? v0 : 0.01f * v0;
                o.y = v1 >= 0.f ? v1 : 0.01f * v1;
                op[n * 4 + tig] = o;
            }
        }
        if (node1 < Nn) {
            float2* op = (float2*)(out + (size_t)node1 * HD + q * 32);
#pragma unroll
            for (int n = 0; n < 4; n++) {
                float v0 = uacc[mt][n][2] * inv1;
                float v1 = uacc[mt][n][3] * inv1;
                float2 o;
                o.x = v0 >= 0.f ? v0 : 0.01f * v0;
                o.y = v1 >= 0.f ? v1 : 0.01f * v1;
                op[n * 4 + tig] = o;
            }
        }
    }
}

// ---------------- launch ----------------
extern "C" void kernel_launch(void* const* d_in, const int* in_sizes, int n_in,
                              void* d_out, int out_size) {
    const float* vt  = (const float*)d_in[0];
    const float* H   = (const float*)d_in[1];
    const float* Wgv = (const float*)d_in[2];
    const float* Wgh = (const float*)d_in[3];
    const float* Wuh = (const float*)d_in[4];
    float* out = (float*)d_out;

    int Nn = in_sizes[0] / HD;

    cudaFuncSetAttribute(het_main, cudaFuncAttributeMaxDynamicSharedMemorySize, SMEM_TOTAL);

    int total = 2048 + KH * 2048 + KH * 4096;   // 51200 prep threads
    prep_kernel<<<(total + 255) / 256, 256>>>(Wgv, Wgh, Wuh);

    int blocks = (Nn + 31) / 32;
    het_main<<<blocks, 128, SMEM_TOTAL>>>(vt, H, out, Nn);
}